// round 1
// baseline (speedup 1.0000x reference)
#include <cuda_runtime.h>

#define BSZ 32
#define SL  512
#define CL  20
#define D   256
#define NH  4
#define HD  64

// ---------------- scratch (device globals; no allocation allowed) ----------
__device__ float g_X[BSZ*SL*D];                 // embedding + PE (residual)
__device__ float g_Q[BSZ*SL*D];
__device__ float g_K[BSZ*SL*D];
__device__ float g_V[BSZ*SL*D];
__device__ float g_S[(size_t)BSZ*NH*SL*SL];     // attention scores/probs (128MB)
__device__ float g_O[BSZ*SL*D];                 // attention output (head concat)
__device__ float g_Z[BSZ*SL*D];                 // FC output
__device__ float g_N[BSZ*SL*D];                 // post-LN, zeroed beyond length

// ---------------- shared GEMM micro-tiles ----------------------------------
#define BM 64
#define BN 64
#define BK 16
#define PAD 4

// C[64,64] tile of A[M,K] @ B[N,K]^T   (both row-major, K contiguous)
__device__ __forceinline__ void gemm_nt_tile(const float* A, const float* B,
    int lda, int ldb, int Kdim, float (&acc)[4][4]) {
    __shared__ float As[BK][BM+PAD];
    __shared__ float Bs[BK][BN+PAD];
    int tid = threadIdx.x;
    int tx = tid & 15, ty = tid >> 4;
    int lr = tid >> 2;            // 0..63  row within tile
    int lk = (tid & 3) << 2;      // 0,4,8,12

    for (int k0 = 0; k0 < Kdim; k0 += BK) {
        float4 a = *(const float4*)(A + lr*lda + k0 + lk);
        float4 b = *(const float4*)(B + lr*ldb + k0 + lk);
        As[lk+0][lr]=a.x; As[lk+1][lr]=a.y; As[lk+2][lr]=a.z; As[lk+3][lr]=a.w;
        Bs[lk+0][lr]=b.x; Bs[lk+1][lr]=b.y; Bs[lk+2][lr]=b.z; Bs[lk+3][lr]=b.w;
        __syncthreads();
        #pragma unroll
        for (int k = 0; k < BK; k++) {
            float4 av = *(const float4*)&As[k][ty<<2];
            float4 bv = *(const float4*)&Bs[k][tx<<2];
            float am[4] = {av.x, av.y, av.z, av.w};
            float bm[4] = {bv.x, bv.y, bv.z, bv.w};
            #pragma unroll
            for (int i = 0; i < 4; i++)
                #pragma unroll
                for (int j = 0; j < 4; j++)
                    acc[i][j] += am[i] * bm[j];
        }
        __syncthreads();
    }
}

// C[64,64] tile of A[M,K] @ B[K,N]   (both row-major)
__device__ __forceinline__ void gemm_nn_tile(const float* A, const float* B,
    int lda, int ldb, int Kdim, float (&acc)[4][4]) {
    __shared__ float As[BK][BM+PAD];
    __shared__ float Bs[BK][BN+PAD];
    int tid = threadIdx.x;
    int tx = tid & 15, ty = tid >> 4;
    int lr = tid >> 2, lk = (tid & 3) << 2;
    int bk = tid >> 4, bn = (tid & 15) << 2;

    for (int k0 = 0; k0 < Kdim; k0 += BK) {
        float4 a = *(const float4*)(A + lr*lda + k0 + lk);
        float4 b = *(const float4*)(B + (k0+bk)*ldb + bn);
        As[lk+0][lr]=a.x; As[lk+1][lr]=a.y; As[lk+2][lr]=a.z; As[lk+3][lr]=a.w;
        *(float4*)&Bs[bk][bn] = b;
        __syncthreads();
        #pragma unroll
        for (int k = 0; k < BK; k++) {
            float4 av = *(const float4*)&As[k][ty<<2];
            float4 bv = *(const float4*)&Bs[k][tx<<2];
            float am[4] = {av.x, av.y, av.z, av.w};
            float bm[4] = {bv.x, bv.y, bv.z, bv.w};
            #pragma unroll
            for (int i = 0; i < 4; i++)
                #pragma unroll
                for (int j = 0; j < 4; j++)
                    acc[i][j] += am[i] * bm[j];
        }
        __syncthreads();
    }
}

// ---------------- K1: embedding sum + bias + positional encoding -----------
__global__ void k_embed(const int* __restrict__ seqs, const int* __restrict__ lengths,
                        const float* __restrict__ emb, const float* __restrict__ bias,
                        const float* __restrict__ pe) {
    int row = blockIdx.x;                 // b*SL + s
    int b = row >> 9, s = row & (SL-1);
    int d = threadIdx.x;
    __shared__ int idx[CL];
    __shared__ int spos;
    if (d < CL) idx[d] = seqs[row*CL + d];
    if (d == 0) spos = (s < lengths[b]) ? (s + 1) : 0;
    __syncthreads();
    float acc = bias[d];
    #pragma unroll
    for (int c = 0; c < CL; c++) acc += emb[idx[c]*D + d];
    acc += pe[spos*D + d];
    g_X[row*D + d] = acc;
}

// ---------------- K2: Q/K/V projections (Y = X @ W^T) ----------------------
__global__ void k_qkv(const float* __restrict__ Wq, const float* __restrict__ Wk,
                      const float* __restrict__ Wv) {
    const float* W = (blockIdx.z == 0) ? Wq : (blockIdx.z == 1) ? Wk : Wv;
    float* C       = (blockIdx.z == 0) ? g_Q : (blockIdx.z == 1) ? g_K : g_V;
    const float* A = g_X + blockIdx.y*64*D;
    const float* B = W   + blockIdx.x*64*D;
    float acc[4][4] = {};
    gemm_nt_tile(A, B, D, D, D, acc);
    int tx = threadIdx.x & 15, ty = threadIdx.x >> 4;
    int m0 = blockIdx.y*64 + (ty<<2), n0 = blockIdx.x*64 + (tx<<2);
    #pragma unroll
    for (int i = 0; i < 4; i++) {
        float4 v = make_float4(acc[i][0], acc[i][1], acc[i][2], acc[i][3]);
        *(float4*)&C[(m0+i)*D + n0] = v;
    }
}

// ---------------- K3: S = Q K^T / 8, masked ---------------------------------
// Head h of Y is rows [h*128,(h+1)*128) viewed as [512,64] contiguous (ld=64).
__global__ void k_scores(const int* __restrict__ masks) {
    int bh = blockIdx.z; int b = bh >> 2, h = bh & 3;
    const float* A = g_Q + b*SL*D + h*SL*HD + blockIdx.y*64*HD;
    const float* B = g_K + b*SL*D + h*SL*HD + blockIdx.x*64*HD;
    float acc[4][4] = {};
    gemm_nt_tile(A, B, HD, HD, HD, acc);
    int tx = threadIdx.x & 15, ty = threadIdx.x >> 4;
    int q0 = blockIdx.y*64 + (ty<<2);
    int k0 = blockIdx.x*64 + (tx<<2);
    float* Sp = g_S + (size_t)bh*SL*SL;
    const int* M = masks + b*SL*SL;
    #pragma unroll
    for (int i = 0; i < 4; i++) {
        float v[4];
        #pragma unroll
        for (int j = 0; j < 4; j++) {
            float t = acc[i][j] * 0.125f;
            if (M[(q0+i)*SL + k0+j] == 0) t = -1e30f;
            v[j] = t;
        }
        *(float4*)&Sp[(size_t)(q0+i)*SL + k0] = make_float4(v[0],v[1],v[2],v[3]);
    }
}

// ---------------- K4: row softmax over 512 keys -----------------------------
__global__ void k_softmax() {
    size_t row = blockIdx.x;
    float* p = g_S + row*SL;
    int t = threadIdx.x;
    float a = p[t], c = p[t+256];
    __shared__ float red[256];
    red[t] = fmaxf(a, c); __syncthreads();
    for (int o = 128; o > 0; o >>= 1) { if (t < o) red[t] = fmaxf(red[t], red[t+o]); __syncthreads(); }
    float mx = red[0]; __syncthreads();
    float ea = __expf(a - mx), ec = __expf(c - mx);
    red[t] = ea + ec; __syncthreads();
    for (int o = 128; o > 0; o >>= 1) { if (t < o) red[t] += red[t+o]; __syncthreads(); }
    float inv = 1.0f / red[0];
    p[t] = ea*inv; p[t+256] = ec*inv;
}

// ---------------- K5: O = P @ V, write in normal head-concat layout ---------
__global__ void k_av() {
    int bh = blockIdx.z; int b = bh >> 2, h = bh & 3;
    const float* A = g_S + (size_t)bh*SL*SL + (size_t)blockIdx.y*64*SL;
    const float* B = g_V + b*SL*D + h*SL*HD;       // [512,64] ld=64
    float acc[4][4] = {};
    gemm_nn_tile(A, B, SL, HD, SL, acc);
    int tx = threadIdx.x & 15, ty = threadIdx.x >> 4;
    int s0 = blockIdx.y*64 + (ty<<2);
    int e0 = tx<<2;
    #pragma unroll
    for (int i = 0; i < 4; i++) {
        float4 v = make_float4(acc[i][0], acc[i][1], acc[i][2], acc[i][3]);
        *(float4*)&g_O[(b*SL + s0+i)*D + h*HD + e0] = v;
    }
}

// ---------------- K6a: Z = O @ Wfc^T ----------------------------------------
__global__ void k_fc(const float* __restrict__ Wfc) {
    const float* A = g_O + blockIdx.y*64*D;
    const float* B = Wfc + blockIdx.x*64*D;
    float acc[4][4] = {};
    gemm_nt_tile(A, B, D, D, D, acc);
    int tx = threadIdx.x & 15, ty = threadIdx.x >> 4;
    int m0 = blockIdx.y*64 + (ty<<2), n0 = blockIdx.x*64 + (tx<<2);
    #pragma unroll
    for (int i = 0; i < 4; i++) {
        float4 v = make_float4(acc[i][0], acc[i][1], acc[i][2], acc[i][3]);
        *(float4*)&g_Z[(m0+i)*D + n0] = v;
    }
}

// ---------------- K6b: residual + LayerNorm + zero invalid ------------------
__global__ void k_ln(const int* __restrict__ lengths, const float* __restrict__ gw,
                     const float* __restrict__ gb) {
    int row = blockIdx.x; int b = row >> 9, s = row & (SL-1);
    int d = threadIdx.x;
    float v = g_Z[row*D + d] + g_X[row*D + d];
    __shared__ float red[256];
    red[d] = v; __syncthreads();
    for (int o = 128; o > 0; o >>= 1) { if (d < o) red[d] += red[d+o]; __syncthreads(); }
    float mu = red[0] * (1.0f/D); __syncthreads();
    float cv = v - mu;
    red[d] = cv*cv; __syncthreads();
    for (int o = 128; o > 0; o >>= 1) { if (d < o) red[d] += red[d+o]; __syncthreads(); }
    float var = red[0] * (1.0f/D);
    float o = cv * rsqrtf(var + 1e-5f) * gw[d] + gb[d];
    g_N[row*D + d] = (s < lengths[b]) ? o : 0.0f;
}

// ---------------- K7: triangular pooling + output linear --------------------
__global__ void k_pool(const int* __restrict__ lengths, const float* __restrict__ ow,
                       const float* __restrict__ ob, float* __restrict__ out) {
    int b = blockIdx.x, d = threadIdx.x;
    int len = lengths[b];
    float inv4 = 4.0f / (float)len;
    float u0=0.f, u1=0.f, u2=0.f, u3=0.f;
    const float* xp = g_N + b*SL*D + d;
    for (int s = 0; s < len; s++) {       // x is exactly 0 beyond len
        float x = xp[s*D];
        float sv = inv4 * (float)(s + 1);
        float w0 = 1.0f - fabsf(sv - 1.0f)*0.25f;
        float w1 = 1.0f - fabsf(sv - 2.0f)*0.25f;
        float w2 = 1.0f - fabsf(sv - 3.0f)*0.25f;
        float w3 = 1.0f - fabsf(sv - 4.0f)*0.25f;
        u0 += w0*w0*x; u1 += w1*w1*x; u2 += w2*w2*x; u3 += w3*w3*x;
    }
    float p0 = u0*ow[d] + u1*ow[256+d] + u2*ow[512+d] + u3*ow[768+d];
    float p1 = u0*ow[1024+d] + u1*ow[1280+d] + u2*ow[1536+d] + u3*ow[1792+d];
    __shared__ float r0[256], r1[256];
    r0[d] = p0; r1[d] = p1; __syncthreads();
    for (int o = 128; o > 0; o >>= 1) {
        if (d < o) { r0[d] += r0[d+o]; r1[d] += r1[d+o]; }
        __syncthreads();
    }
    if (d == 0) { out[b*2+0] = r0[0] + ob[0]; out[b*2+1] = r1[0] + ob[1]; }
}

// ---------------- launch -----------------------------------------------------
extern "C" void kernel_launch(void* const* d_in, const int* in_sizes, int n_in,
                              void* d_out, int out_size) {
    const int*   seqs    = (const int*)  d_in[0];
    const int*   masks   = (const int*)  d_in[1];
    const int*   lengths = (const int*)  d_in[2];
    // d_in[3] seq_time_step, d_in[4] code_masks: unused by reference
    const float* emb     = (const float*)d_in[5];
    const float* bias    = (const float*)d_in[6];
    const float* pe      = (const float*)d_in[7];
    const float* Wq      = (const float*)d_in[8];
    const float* Wk      = (const float*)d_in[9];
    const float* Wv      = (const float*)d_in[10];
    const float* Wfc     = (const float*)d_in[11];
    const float* lng     = (const float*)d_in[12];
    const float* lnb     = (const float*)d_in[13];
    const float* ow      = (const float*)d_in[14];
    const float* ob      = (const float*)d_in[15];
    float* out = (float*)d_out;

    k_embed  <<<BSZ*SL, 256>>>(seqs, lengths, emb, bias, pe);
    k_qkv    <<<dim3(D/64, BSZ*SL/64, 3), 256>>>(Wq, Wk, Wv);
    k_scores <<<dim3(SL/64, SL/64, BSZ*NH), 256>>>(masks);
    k_softmax<<<BSZ*NH*SL, 256>>>();
    k_av     <<<dim3(1, SL/64, BSZ*NH), 256>>>();
    k_fc     <<<dim3(D/64, BSZ*SL/64, 1), 256>>>(Wfc);
    k_ln     <<<BSZ*SL, 256>>>(lengths, lng, lnb);
    k_pool   <<<BSZ, 256>>>(lengths, ow, ob, out);
}

// round 2
// speedup vs baseline: 1.2679x; 1.2679x over previous
#include <cuda_runtime.h>

#define BSZ 32
#define SL  512
#define CL  20
#define D   256
#define NH  4
#define HD  64

typedef unsigned long long u64;

// ---------------- scratch (device globals; no allocation allowed) ----------
__device__ float g_X[BSZ*SL*D];                 // embedding + PE (residual)
__device__ float g_Q[BSZ*SL*D];
__device__ float g_K[BSZ*SL*D];
__device__ float g_V[BSZ*SL*D];
__device__ float g_O[BSZ*SL*D];                 // attention output (head concat)
__device__ float g_Z[BSZ*SL*D];                 // FC output
__device__ float g_N[BSZ*SL*D];                 // post-LN, zeroed beyond length

// ---------------- packed f32x2 helpers --------------------------------------
__device__ __forceinline__ u64 dupf(float x){u64 d;asm("mov.b64 %0,{%1,%1};":"=l"(d):"f"(x));return d;}
__device__ __forceinline__ u64 pack2(float lo,float hi){u64 d;asm("mov.b64 %0,{%1,%2};":"=l"(d):"f"(lo),"f"(hi));return d;}
__device__ __forceinline__ void unpack2(u64 d,float&lo,float&hi){asm("mov.b64 {%0,%1},%2;":"=f"(lo),"=f"(hi):"l"(d));}
__device__ __forceinline__ void fma2(u64&a,u64 x,u64 y){asm("fma.rn.f32x2 %0,%1,%2,%0;":"+l"(a):"l"(x),"l"(y));}
__device__ __forceinline__ u64 mul2(u64 x,u64 y){u64 r;asm("mul.rn.f32x2 %0,%1,%2;":"=l"(r):"l"(x),"l"(y));return r;}

#define FMA2_16(ACC,A0,A1,A2,A3,B0,B1,B2,B3) \
    fma2(ACC[0][0],A0,B0); fma2(ACC[0][1],A0,B1); fma2(ACC[0][2],A0,B2); fma2(ACC[0][3],A0,B3); \
    fma2(ACC[1][0],A1,B0); fma2(ACC[1][1],A1,B1); fma2(ACC[1][2],A1,B2); fma2(ACC[1][3],A1,B3); \
    fma2(ACC[2][0],A2,B0); fma2(ACC[2][1],A2,B1); fma2(ACC[2][2],A2,B2); fma2(ACC[2][3],A2,B3); \
    fma2(ACC[3][0],A3,B0); fma2(ACC[3][1],A3,B1); fma2(ACC[3][2],A3,B2); fma2(ACC[3][3],A3,B3);

// ---------------- K1: embedding sum + bias + positional encoding -----------
__global__ void k_embed(const int* __restrict__ seqs, const int* __restrict__ lengths,
                        const float* __restrict__ emb, const float* __restrict__ bias,
                        const float* __restrict__ pe) {
    int row = blockIdx.x;                 // b*SL + s
    int b = row >> 9, s = row & (SL-1);
    int d = threadIdx.x;
    __shared__ int idx[CL];
    __shared__ int spos;
    if (d < CL) idx[d] = seqs[row*CL + d];
    if (d == 0) spos = (s < lengths[b]) ? (s + 1) : 0;
    __syncthreads();
    float acc = bias[d];
    #pragma unroll
    for (int c = 0; c < CL; c++) acc += emb[idx[c]*D + d];
    acc += pe[spos*D + d];
    g_X[row*D + d] = acc;
}

// ---------------- NT GEMM tile 128x64, K contiguous in both, lda=ldb=K=D ----
__device__ __forceinline__ void gemm_nt_128x64(const float* __restrict__ A,
        const float* __restrict__ B, float* __restrict__ Cg) {
    __shared__ __align__(16) float As[16][128+4];
    __shared__ __align__(16) float Bs[16][64+4];
    u64 acc[4][4] = {};
    int tid = threadIdx.x, tx = tid&15, ty = tid>>4;
    int ar = tid>>1, ak = (tid&1)*8;
    int br = tid>>2, bk = (tid&3)*4;
    for (int k0 = 0; k0 < D; k0 += 16) {
        float4 a0 = *(const float4*)(A + ar*D + k0 + ak);
        float4 a1 = *(const float4*)(A + ar*D + k0 + ak + 4);
        float4 b0 = *(const float4*)(B + br*D + k0 + bk);
        As[ak+0][ar]=a0.x; As[ak+1][ar]=a0.y; As[ak+2][ar]=a0.z; As[ak+3][ar]=a0.w;
        As[ak+4][ar]=a1.x; As[ak+5][ar]=a1.y; As[ak+6][ar]=a1.z; As[ak+7][ar]=a1.w;
        Bs[bk+0][br]=b0.x; Bs[bk+1][br]=b0.y; Bs[bk+2][br]=b0.z; Bs[bk+3][br]=b0.w;
        __syncthreads();
        #pragma unroll
        for (int k = 0; k < 16; k++) {
            const u64* pA = (const u64*)&As[k][ty*8];
            u64 a0d=pA[0], a1d=pA[1], a2d=pA[2], a3d=pA[3];
            float4 bv = *(const float4*)&Bs[k][tx*4];
            u64 b0d=dupf(bv.x), b1d=dupf(bv.y), b2d=dupf(bv.z), b3d=dupf(bv.w);
            FMA2_16(acc, a0d,a1d,a2d,a3d, b0d,b1d,b2d,b3d)
        }
        __syncthreads();
    }
    int m0 = ty*8, n0 = tx*4;
    #pragma unroll
    for (int p = 0; p < 4; p++) {
        float l0,h0,l1,h1,l2,h2,l3,h3;
        unpack2(acc[p][0],l0,h0); unpack2(acc[p][1],l1,h1);
        unpack2(acc[p][2],l2,h2); unpack2(acc[p][3],l3,h3);
        *(float4*)&Cg[(m0+2*p  )*D + n0] = make_float4(l0,l1,l2,l3);
        *(float4*)&Cg[(m0+2*p+1)*D + n0] = make_float4(h0,h1,h2,h3);
    }
}

// ---------------- K2: Q/K/V projections -------------------------------------
__global__ void __launch_bounds__(256) k_qkv(const float* __restrict__ Wq,
        const float* __restrict__ Wk, const float* __restrict__ Wv) {
    const float* W = (blockIdx.z==0) ? Wq : (blockIdx.z==1) ? Wk : Wv;
    float* C       = (blockIdx.z==0) ? g_Q : (blockIdx.z==1) ? g_K : g_V;
    gemm_nt_128x64(g_X + blockIdx.y*128*D, W + blockIdx.x*64*D,
                   C + blockIdx.y*128*D + blockIdx.x*64);
}

// ---------------- K3: fused flash attention ---------------------------------
// Head h of Y is rows [h*128,(h+1)*128) viewed as [512,64] contiguous (ld=64).
#define QSTR 132
#define KSTR 68
__global__ void __launch_bounds__(256) k_flash(const int* __restrict__ masks) {
    extern __shared__ __align__(16) float sm[];
    float* Qs = sm;                 // [64 hd][QSTR]  (hd-major, q contiguous)
    float* Ps = sm + 64*QSTR;       // [64 key][QSTR] (key-major, q contiguous)
    float* Ks = sm + 2*64*QSTR;     // [64 hd][KSTR]  (hd-major, key contiguous)
    float* Vs = Ks + 64*KSTR;       // [64 key][KSTR] (key-major, hd contiguous)
    int bh = blockIdx.y, b = bh>>2, h = bh&3;
    int q0 = blockIdx.x*128;
    const float* Qg = g_Q + b*SL*D + h*SL*HD + q0*HD;
    const float* Kg = g_K + b*SL*D + h*SL*HD;
    const float* Vg = g_V + b*SL*D + h*SL*HD;
    const int*   Mg = masks + b*SL*SL;
    int tid = threadIdx.x, tx = tid&15, ty = tid>>4;

    { // Q tile [128 q][64 hd] -> Qs transposed
        int qr = tid>>1, c0 = (tid&1)*32;
        #pragma unroll
        for (int c = 0; c < 32; c += 4) {
            float4 v = *(const float4*)(Qg + qr*HD + c0 + c);
            Qs[(c0+c+0)*QSTR+qr]=v.x; Qs[(c0+c+1)*QSTR+qr]=v.y;
            Qs[(c0+c+2)*QSTR+qr]=v.z; Qs[(c0+c+3)*QSTR+qr]=v.w;
        }
    }
    u64 accO[4][4] = {};
    float mrow[8], lrow[8];
    #pragma unroll
    for (int i = 0; i < 8; i++) { mrow[i] = -3.0e38f; lrow[i] = 0.0f; }

    int kr = tid>>2, c0 = (tid&3)*16;
    for (int kt = 0; kt < 8; kt++) {
        int k0 = kt*64;
        __syncthreads();
        #pragma unroll
        for (int c = 0; c < 16; c += 4) {
            float4 kv = *(const float4*)(Kg + (k0+kr)*HD + c0 + c);
            Ks[(c0+c+0)*KSTR+kr]=kv.x; Ks[(c0+c+1)*KSTR+kr]=kv.y;
            Ks[(c0+c+2)*KSTR+kr]=kv.z; Ks[(c0+c+3)*KSTR+kr]=kv.w;
            float4 vv = *(const float4*)(Vg + (k0+kr)*HD + c0 + c);
            *(float4*)&Vs[kr*KSTR + c0 + c] = vv;
        }
        __syncthreads();
        // S = Q @ K^T tile [128 q][64 key]
        u64 accS[4][4] = {};
        #pragma unroll 16
        for (int k = 0; k < 64; k++) {
            const u64* pA = (const u64*)&Qs[k*QSTR + ty*8];
            u64 a0=pA[0],a1=pA[1],a2=pA[2],a3=pA[3];
            float4 bv = *(const float4*)&Ks[k*KSTR + tx*4];
            u64 b0=dupf(bv.x),b1=dupf(bv.y),b2=dupf(bv.z),b3=dupf(bv.w);
            FMA2_16(accS, a0,a1,a2,a3, b0,b1,b2,b3)
        }
        // online softmax per row-pair
        #pragma unroll
        for (int p = 0; p < 4; p++) {
            float s0[4], s1[4];
            unpack2(accS[p][0],s0[0],s1[0]); unpack2(accS[p][1],s0[1],s1[1]);
            unpack2(accS[p][2],s0[2],s1[2]); unpack2(accS[p][3],s0[3],s1[3]);
            int r0 = q0 + ty*8 + 2*p;
            int4 mk0 = *(const int4*)(Mg + r0*SL + k0 + tx*4);
            int4 mk1 = *(const int4*)(Mg + (r0+1)*SL + k0 + tx*4);
            s0[0] = mk0.x ? s0[0]*0.125f : -1e30f;
            s0[1] = mk0.y ? s0[1]*0.125f : -1e30f;
            s0[2] = mk0.z ? s0[2]*0.125f : -1e30f;
            s0[3] = mk0.w ? s0[3]*0.125f : -1e30f;
            s1[0] = mk1.x ? s1[0]*0.125f : -1e30f;
            s1[1] = mk1.y ? s1[1]*0.125f : -1e30f;
            s1[2] = mk1.z ? s1[2]*0.125f : -1e30f;
            s1[3] = mk1.w ? s1[3]*0.125f : -1e30f;
            float mx0 = fmaxf(fmaxf(s0[0],s0[1]), fmaxf(s0[2],s0[3]));
            float mx1 = fmaxf(fmaxf(s1[0],s1[1]), fmaxf(s1[2],s1[3]));
            #pragma unroll
            for (int o = 8; o > 0; o >>= 1) {
                mx0 = fmaxf(mx0, __shfl_xor_sync(0xffffffffu, mx0, o, 16));
                mx1 = fmaxf(mx1, __shfl_xor_sync(0xffffffffu, mx1, o, 16));
            }
            float nm0 = fmaxf(mrow[2*p],   mx0);
            float nm1 = fmaxf(mrow[2*p+1], mx1);
            float cf0 = __expf(mrow[2*p]   - nm0);
            float cf1 = __expf(mrow[2*p+1] - nm1);
            mrow[2*p] = nm0; mrow[2*p+1] = nm1;
            float rs0 = 0.f, rs1 = 0.f;
            #pragma unroll
            for (int j = 0; j < 4; j++) {
                s0[j] = __expf(s0[j] - nm0); rs0 += s0[j];
                s1[j] = __expf(s1[j] - nm1); rs1 += s1[j];
            }
            #pragma unroll
            for (int o = 8; o > 0; o >>= 1) {
                rs0 += __shfl_xor_sync(0xffffffffu, rs0, o, 16);
                rs1 += __shfl_xor_sync(0xffffffffu, rs1, o, 16);
            }
            lrow[2*p]   = lrow[2*p]  *cf0 + rs0;
            lrow[2*p+1] = lrow[2*p+1]*cf1 + rs1;
            u64 cp = pack2(cf0, cf1);
            #pragma unroll
            for (int j = 0; j < 4; j++) accO[p][j] = mul2(accO[p][j], cp);
            #pragma unroll
            for (int j = 0; j < 4; j++) {
                Ps[(tx*4+j)*QSTR + ty*8 + 2*p    ] = s0[j];
                Ps[(tx*4+j)*QSTR + ty*8 + 2*p + 1] = s1[j];
            }
        }
        __syncthreads();
        // O += P @ V  ([128 q][64 hd])
        #pragma unroll 16
        for (int k = 0; k < 64; k++) {
            const u64* pA = (const u64*)&Ps[k*QSTR + ty*8];
            u64 a0=pA[0],a1=pA[1],a2=pA[2],a3=pA[3];
            float4 bv = *(const float4*)&Vs[k*KSTR + tx*4];
            u64 b0=dupf(bv.x),b1=dupf(bv.y),b2=dupf(bv.z),b3=dupf(bv.w);
            FMA2_16(accO, a0,a1,a2,a3, b0,b1,b2,b3)
        }
    }
    // finalize: O /= l, write head-concat layout
    #pragma unroll
    for (int p = 0; p < 4; p++) {
        u64 il = pack2(1.0f/lrow[2*p], 1.0f/lrow[2*p+1]);
        u64 t0 = mul2(accO[p][0], il), t1 = mul2(accO[p][1], il);
        u64 t2 = mul2(accO[p][2], il), t3 = mul2(accO[p][3], il);
        float l0,h0,l1,h1,l2,h2,l3,h3;
        unpack2(t0,l0,h0); unpack2(t1,l1,h1); unpack2(t2,l2,h2); unpack2(t3,l3,h3);
        int row = b*SL + q0 + ty*8 + 2*p;
        int col = h*HD + tx*4;
        *(float4*)&g_O[row*D + col]     = make_float4(l0,l1,l2,l3);
        *(float4*)&g_O[(row+1)*D + col] = make_float4(h0,h1,h2,h3);
    }
}

// ---------------- K4: Z = O @ Wfc^T ------------------------------------------
__global__ void __launch_bounds__(256) k_fc(const float* __restrict__ Wfc) {
    gemm_nt_128x64(g_O + blockIdx.y*128*D, Wfc + blockIdx.x*64*D,
                   g_Z + blockIdx.y*128*D + blockIdx.x*64);
}

// ---------------- K5: residual + LayerNorm + zero invalid --------------------
__global__ void k_ln(const int* __restrict__ lengths, const float* __restrict__ gw,
                     const float* __restrict__ gb) {
    int row = blockIdx.x; int b = row >> 9, s = row & (SL-1);
    int d = threadIdx.x;
    float v = g_Z[row*D + d] + g_X[row*D + d];
    __shared__ float red[256];
    red[d] = v; __syncthreads();
    for (int o = 128; o > 0; o >>= 1) { if (d < o) red[d] += red[d+o]; __syncthreads(); }
    float mu = red[0] * (1.0f/D); __syncthreads();
    float cv = v - mu;
    red[d] = cv*cv; __syncthreads();
    for (int o = 128; o > 0; o >>= 1) { if (d < o) red[d] += red[d+o]; __syncthreads(); }
    float var = red[0] * (1.0f/D);
    float o = cv * rsqrtf(var + 1e-5f) * gw[d] + gb[d];
    g_N[row*D + d] = (s < lengths[b]) ? o : 0.0f;
}

// ---------------- K6: triangular pooling + output linear ---------------------
__global__ void k_pool(const int* __restrict__ lengths, const float* __restrict__ ow,
                       const float* __restrict__ ob, float* __restrict__ out) {
    int b = blockIdx.x, d = threadIdx.x;
    int len = lengths[b];
    float inv4 = 4.0f / (float)len;
    float u0=0.f, u1=0.f, u2=0.f, u3=0.f;
    const float* xp = g_N + b*SL*D + d;
    for (int s = 0; s < len; s++) {       // x is exactly 0 beyond len
        float x = xp[s*D];
        float sv = inv4 * (float)(s + 1);
        float w0 = 1.0f - fabsf(sv - 1.0f)*0.25f;
        float w1 = 1.0f - fabsf(sv - 2.0f)*0.25f;
        float w2 = 1.0f - fabsf(sv - 3.0f)*0.25f;
        float w3 = 1.0f - fabsf(sv - 4.0f)*0.25f;
        u0 += w0*w0*x; u1 += w1*w1*x; u2 += w2*w2*x; u3 += w3*w3*x;
    }
    float p0 = u0*ow[d] + u1*ow[256+d] + u2*ow[512+d] + u3*ow[768+d];
    float p1 = u0*ow[1024+d] + u1*ow[1280+d] + u2*ow[1536+d] + u3*ow[1792+d];
    __shared__ float r0[256], r1[256];
    r0[d] = p0; r1[d] = p1; __syncthreads();
    for (int o = 128; o > 0; o >>= 1) {
        if (d < o) { r0[d] += r0[d+o]; r1[d] += r1[d+o]; }
        __syncthreads();
    }
    if (d == 0) { out[b*2+0] = r0[0] + ob[0]; out[b*2+1] = r1[0] + ob[1]; }
}

// ---------------- launch -----------------------------------------------------
extern "C" void kernel_launch(void* const* d_in, const int* in_sizes, int n_in,
                              void* d_out, int out_size) {
    const int*   seqs    = (const int*)  d_in[0];
    const int*   masks   = (const int*)  d_in[1];
    const int*   lengths = (const int*)  d_in[2];
    const float* emb     = (const float*)d_in[5];
    const float* bias    = (const float*)d_in[6];
    const float* pe      = (const float*)d_in[7];
    const float* Wq      = (const float*)d_in[8];
    const float* Wk      = (const float*)d_in[9];
    const float* Wv      = (const float*)d_in[10];
    const float* Wfc     = (const float*)d_in[11];
    const float* lng     = (const float*)d_in[12];
    const float* lnb     = (const float*)d_in[13];
    const float* ow      = (const float*)d_in[14];
    const float* ob      = (const float*)d_in[15];
    float* out = (float*)d_out;

    const int flash_smem = (2*64*QSTR + 2*64*KSTR) * 4;   // 102400 bytes
    cudaFuncSetAttribute(k_flash, cudaFuncAttributeMaxDynamicSharedMemorySize, flash_smem);

    k_embed<<<BSZ*SL, 256>>>(seqs, lengths, emb, bias, pe);
    k_qkv  <<<dim3(D/64, BSZ*SL/128, 3), 256>>>(Wq, Wk, Wv);
    k_flash<<<dim3(SL/128, BSZ*NH), 256, flash_smem>>>(masks);
    k_fc   <<<dim3(D/64, BSZ*SL/128, 1), 256>>>(Wfc);
    k_ln   <<<BSZ*SL, 256>>>(lengths, lng, lnb);
    k_pool <<<BSZ, 256>>>(lengths, ow, ob, out);
}